// round 2
// baseline (speedup 1.0000x reference)
#include <cuda_runtime.h>
#include <math.h>

#define OC 32
#define MAXN 100000

// ---- scratch (device globals; no allocation allowed) ----
// NOTE: these are referenced ONLY from device code. Passing a __device__
// symbol as a host-side kernel argument yields the host shadow address
// (silently "works" on GB300 via ATS but touches host memory) — that was
// the round-1 bug.
__device__ float g_y_tp   [MAXN * OC];
__device__ float g_y_int  [MAXN * OC];
__device__ float g_acc_tp1 [MAXN * OC];
__device__ float g_acc_int1[MAXN * OC];
__device__ float g_acc_tp2 [MAXN * OC];
__device__ float g_acc_int2[MAXN * OC];
__device__ float g_h      [MAXN * OC];
__device__ float g_inv    [MAXN];
__device__ int   g_cnt    [MAXN];

// ------------------------------------------------------------------
// zero accumulators + counts
__global__ void k_zero(int n_node) {
    int i = blockIdx.x * blockDim.x + threadIdx.x;
    int tot = n_node * OC;
    if (i < tot) {
        g_acc_tp1[i]  = 0.f;
        g_acc_int1[i] = 0.f;
        g_acc_tp2[i]  = 0.f;
        g_acc_int2[i] = 0.f;
    }
    if (i < n_node) g_cnt[i] = 0;
}

// degree of 'intersects' dst (same edges for both blocks)
__global__ void k_count(const int* __restrict__ dst, int E) {
    int e = blockIdx.x * blockDim.x + threadIdx.x;
    if (e < E) atomicAdd(&g_cnt[dst[e]], 1);
}

__global__ void k_inv(int n_node) {
    int i = blockIdx.x * blockDim.x + threadIdx.x;
    if (i < n_node) g_inv[i] = 1.f / fmaxf((float)g_cnt[i], 1.f);
}

// ------------------------------------------------------------------
// block-1 transforms: y_tp = x @ W_tp1, y_int = x @ W_int1   (Cin = 6)
// warp per node, lane = output channel
__global__ void k_transform6(const float* __restrict__ x,
                             const float* __restrict__ Wtp,
                             const float* __restrict__ Wint,
                             int n_node) {
    int t = blockIdx.x * blockDim.x + threadIdx.x;
    int node = t >> 5;
    int c = t & 31;
    if (node >= n_node) return;
    float a = 0.f, b = 0.f;
#pragma unroll
    for (int k = 0; k < 6; k++) {
        float xv = __ldg(&x[node * 6 + k]);
        a = fmaf(xv, __ldg(&Wtp[k * OC + c]), a);
        b = fmaf(xv, __ldg(&Wint[k * OC + c]), b);
    }
    g_y_tp[node * OC + c]  = a;
    g_y_int[node * OC + c] = b;
}

// ------------------------------------------------------------------
// edge scatter: acc[dst] += y[src].  thread = (edge, channel-quad).
// 'which' selects the y / acc arrays IN DEVICE CODE:
//   0: y_tp  -> acc_tp1     1: y_int -> acc_int1
//   2: y_tp  -> acc_tp2     3: y_int -> acc_int2
__global__ void k_scatter(const int* __restrict__ src,
                          const int* __restrict__ dst,
                          int which, int E) {
    const float* __restrict__ y = (which & 1) ? g_y_int : g_y_tp;
    float* acc;
    switch (which) {
        case 0:  acc = g_acc_tp1;  break;
        case 1:  acc = g_acc_int1; break;
        case 2:  acc = g_acc_tp2;  break;
        default: acc = g_acc_int2; break;
    }
    long long t = (long long)blockIdx.x * blockDim.x + threadIdx.x;
    int e = (int)(t >> 3);
    int q = (int)(t & 7);
    if (e >= E) return;
    int s = __ldg(&src[e]);
    int d = __ldg(&dst[e]);
    float4 v = *(const float4*)(y + (long long)s * OC + q * 4);
    float* p = acc + (long long)d * OC + q * 4;
    atomicAdd(p + 0, v.x);
    atomicAdd(p + 1, v.y);
    atomicAdd(p + 2, v.z);
    atomicAdd(p + 3, v.w);
}

// ------------------------------------------------------------------
// combine block 1 (relu(x@(Ws+Wres) + b + m_tp + m_int)) fused with
// block-2 transforms (y_tp2/y_int2 = h @ W) via warp shuffles.
// warp per node, lane = channel.
__global__ void k_combine1(const float* __restrict__ x,
                           const float* __restrict__ Ws,
                           const float* __restrict__ b,
                           const float* __restrict__ Wres,
                           const float* __restrict__ Wtp2,
                           const float* __restrict__ Wint2,
                           int n_node) {
    __shared__ float sWtp[OC * OC];
    __shared__ float sWint[OC * OC];
    for (int i = threadIdx.x; i < OC * OC; i += blockDim.x) {
        sWtp[i]  = Wtp2[i];
        sWint[i] = Wint2[i];
    }
    __syncthreads();

    int t = blockIdx.x * blockDim.x + threadIdx.x;
    int node = t >> 5;
    int c = t & 31;
    if (node >= n_node) return;

    float acc = __ldg(&b[c]);
#pragma unroll
    for (int k = 0; k < 6; k++) {
        float xv = __ldg(&x[node * 6 + k]);
        acc = fmaf(xv, __ldg(&Ws[k * OC + c]) + __ldg(&Wres[k * OC + c]), acc);
    }
    int o = node * OC + c;
    acc += g_acc_tp1[o] + g_acc_int1[o] * g_inv[node];
    float h = fmaxf(acc, 0.f);
    g_h[o] = h;

    // block-2 transforms on the fresh h (broadcast h across the warp)
    float atp = 0.f, ain = 0.f;
#pragma unroll
    for (int k = 0; k < OC; k++) {
        float hk = __shfl_sync(0xffffffffu, h, k);
        atp = fmaf(hk, sWtp[k * OC + c], atp);
        ain = fmaf(hk, sWint[k * OC + c], ain);
    }
    g_y_tp[o]  = atp;
    g_y_int[o] = ain;
}

// ------------------------------------------------------------------
// combine block 2 (identity residual) fused with the decoder MLP +
// sigmoid.  warp per node, lane = channel.
__global__ void k_combine2(const float* __restrict__ Ws2,
                           const float* __restrict__ b2,
                           const float* __restrict__ Wd1,
                           const float* __restrict__ bd1,
                           const float* __restrict__ Wd2,
                           const float* __restrict__ bd2,
                           float* __restrict__ out,
                           int n_node) {
    __shared__ float sWs[OC * OC];
    __shared__ float sWd1[OC * OC];
    for (int i = threadIdx.x; i < OC * OC; i += blockDim.x) {
        sWs[i]  = Ws2[i];
        sWd1[i] = Wd1[i];
    }
    __syncthreads();

    int t = blockIdx.x * blockDim.x + threadIdx.x;
    int node = t >> 5;
    int c = t & 31;
    if (node >= n_node) return;

    int o = node * OC + c;
    float h = g_h[o];
    float acc = __ldg(&b2[c]) + h;   // identity residual
#pragma unroll
    for (int k = 0; k < OC; k++) {
        float hk = __shfl_sync(0xffffffffu, h, k);
        acc = fmaf(hk, sWs[k * OC + c], acc);
    }
    acc += g_acc_tp2[o] + g_acc_int2[o] * g_inv[node];
    float h2 = fmaxf(acc, 0.f);

    // decoder layer 1
    float d = __ldg(&bd1[c]);
#pragma unroll
    for (int k = 0; k < OC; k++) {
        float hk = __shfl_sync(0xffffffffu, h2, k);
        d = fmaf(hk, sWd1[k * OC + c], d);
    }
    d = fmaxf(d, 0.f) * __ldg(&Wd2[c]);

    // decoder layer 2: warp-reduce dot product
#pragma unroll
    for (int off = 16; off > 0; off >>= 1)
        d += __shfl_xor_sync(0xffffffffu, d, off);

    if (c == 0)
        out[node] = 1.f / (1.f + __expf(-(d + __ldg(&bd2[0]))));
}

// ------------------------------------------------------------------
extern "C" void kernel_launch(void* const* d_in, const int* in_sizes, int n_in,
                              void* d_out, int out_size) {
    const float* x        = (const float*)d_in[0];
    const int*   edge_tp  = (const int*)d_in[1];
    const int*   edge_int = (const int*)d_in[2];
    const float* W_self1  = (const float*)d_in[3];
    const float* b1       = (const float*)d_in[4];
    const float* W_tp1    = (const float*)d_in[5];
    const float* W_int1   = (const float*)d_in[6];
    const float* W_res1   = (const float*)d_in[7];
    const float* W_self2  = (const float*)d_in[8];
    const float* b2       = (const float*)d_in[9];
    const float* W_tp2    = (const float*)d_in[10];
    const float* W_int2   = (const float*)d_in[11];
    const float* Wd1      = (const float*)d_in[12];
    const float* bd1      = (const float*)d_in[13];
    const float* Wd2      = (const float*)d_in[14];
    const float* bd2      = (const float*)d_in[15];
    float* out = (float*)d_out;

    const int N = in_sizes[0] / 6;        // 100000
    const int E = in_sizes[1] / 2;        // 1600000

    const int* tp_src  = edge_tp;
    const int* tp_dst  = edge_tp + E;
    const int* int_src = edge_int;
    const int* int_dst = edge_int + E;

    const int TB = 256;
    const int gNode  = (N * OC + TB - 1) / TB;          // warp-per-node kernels
    const int gEdge  = (E + TB - 1) / TB;
    const int gEdge8 = (int)(((long long)E * 8 + TB - 1) / TB);
    const int gN     = (N + TB - 1) / TB;

    // prologue: zero + degree
    k_zero<<<gNode, TB>>>(N);
    k_count<<<gEdge, TB>>>(int_dst, E);
    k_inv<<<gN, TB>>>(N);

    // block 1
    k_transform6<<<gNode, TB>>>(x, W_tp1, W_int1, N);
    k_scatter<<<gEdge8, TB>>>(tp_src, tp_dst, 0, E);
    k_scatter<<<gEdge8, TB>>>(int_src, int_dst, 1, E);
    k_combine1<<<gNode, TB>>>(x, W_self1, b1, W_res1, W_tp2, W_int2, N);

    // block 2 (y_tp/y_int for block 2 were written by k_combine1)
    k_scatter<<<gEdge8, TB>>>(tp_src, tp_dst, 2, E);
    k_scatter<<<gEdge8, TB>>>(int_src, int_dst, 3, E);

    // combine block 2 + decoder + sigmoid
    k_combine2<<<gNode, TB>>>(W_self2, b2, Wd1, bd1, Wd2, bd2, out, N);
}